// round 10
// baseline (speedup 1.0000x reference)
#include <cuda_runtime.h>

#define HID   32
#define INDIM 128
#define NMAX  100000
#define EMAX  1600000
#define BMW   ((NMAX + 31) / 32)    // 3125 bitmap words = 12.5 KB
#define SBUF  2048                  // per-block smem edge buffer

// ---------------- static device scratch (no allocations allowed) ----------------
// Everything mutable is reset by k_tail each call, so every graph replay sees
// identical initial state. Statics start zeroed.
__device__ __align__(16) float        g_deg [NMAX];   // only F0 entries touched; reset via list0
__device__ __align__(16) float        g_dinv[NMAX];   // recomputed for F0 each call
__device__ __align__(16) unsigned int g_bm0[BMW], g_bm1[BMW], g_bm2[BMW];  // reset in tail
__device__ int  g_list0[NMAX], g_list1[NMAX], g_list2[NMAX];
__device__ int2 g_L1[EMAX], g_L2[EMAX], g_L3[EMAX];
__device__ int  g_c0, g_c1, g_c2, g_cL1, g_cL2, g_cL3;                    // reset in tail
__device__ __align__(16) float g_y0[(size_t)NMAX * HID];
__device__ __align__(16) float g_y1[(size_t)NMAX * HID];
__device__ __align__(16) float g_y2[(size_t)NMAX * HID];
__device__ __align__(16) float g_a1[(size_t)NMAX * HID];  // rows zeroed on frontier insert
__device__ __align__(16) float g_a2[(size_t)NMAX * HID];
__device__ __align__(16) float g_a3[2 * HID];             // reset in tail

// ---------------- frontier insertion: atomicOr dedupe + cascade ----------------
__device__ __forceinline__ void add_f0(int n) {
    unsigned int b = 1u << (n & 31);
    if (!(atomicOr(&g_bm0[n >> 5], b) & b))
        g_list0[atomicAdd(&g_c0, 1)] = n;
}
__device__ __forceinline__ void add_f1(int n) {
    unsigned int b = 1u << (n & 31);
    if (!(atomicOr(&g_bm1[n >> 5], b) & b)) {
        g_list1[atomicAdd(&g_c1, 1)] = n;
        float4* a = (float4*)(g_a1 + (size_t)n * HID);
        float4 z = make_float4(0.f, 0.f, 0.f, 0.f);
        #pragma unroll
        for (int j = 0; j < 8; j++) a[j] = z;
        add_f0(n);
    }
}
__device__ __forceinline__ void add_f2(int n) {
    unsigned int b = 1u << (n & 31);
    if (!(atomicOr(&g_bm2[n >> 5], b) & b)) {
        g_list2[atomicAdd(&g_c2, 1)] = n;
        float4* a = (float4*)(g_a2 + (size_t)n * HID);
        float4 z = make_float4(0.f, 0.f, 0.f, 0.f);
        #pragma unroll
        for (int j = 0; j < 8; j++) a[j] = z;
        add_f1(n);
    }
}

// ---------------- edge scan kernel, templated on phase --------------------------
// MODE 0: dst<2          -> L3 + cascade F2     (unmasked)
// MODE 1: bm2[dst]       -> L2 + cascade F1     (smem bitmap)
// MODE 2: bm1[dst]       -> L1 + cascade F0
// MODE 3: bm0[dst]       -> deg atomic only
// 1024 threads/block, 16 edges/thread via vectorized dst loads (2-4 edges/LDG).
template<int MODE>
__global__ void __launch_bounds__(1024) k_scan(const void* __restrict__ ei, int E) {
    __shared__ unsigned int s_bm[BMW];
    __shared__ int2 s_buf[(MODE == 1 || MODE == 2) ? SBUF : 1];
    __shared__ int  s_n, s_base, s_i64;

    const int tid = threadIdx.x;
    if (tid == 0) { s_n = 0; s_i64 = 1; }
    __syncthreads();

    // parallel int64/int32 detection: int64 => high word of every element is 0
    {
        const unsigned int* w = (const unsigned int*)ei;
        int lim = (2 * E < 2048) ? 2 * E : 2048;
        for (int k = 2 * tid + 1; k < lim; k += 2048)
            if (w[k]) s_i64 = 0;                   // benign same-value race
    }
    if (MODE >= 1) {
        const unsigned int* bm = (MODE == 1) ? g_bm2 : (MODE == 2) ? g_bm1 : g_bm0;
        for (int i = tid; i < BMW; i += 1024) s_bm[i] = bm[i];
    }
    __syncthreads();
    const int i64 = s_i64;

    int2* Lg = (MODE == 0) ? g_L3 : (MODE == 1) ? g_L2 : g_L1;
    int*  cg = (MODE == 0) ? &g_cL3 : (MODE == 1) ? &g_cL2 : &g_cL1;

    if (MODE == 0 && blockIdx.x == 0 && tid == 0) { add_f2(0); add_f2(1); }

    auto process = [&](int e, int d) {
        bool hit = (MODE == 0) ? (d < 2) : (((s_bm[d >> 5] >> (d & 31)) & 1u) != 0);
        if (!hit) return;
        if (MODE == 3) { atomicAdd(&g_deg[d], 1.0f); return; }
        int s = i64 ? (int)((const long long*)ei)[e] : ((const int*)ei)[e];
        if (MODE == 0) {
            Lg[atomicAdd(cg, 1)] = make_int2(s, d);      // ~tens of hits
            add_f2(s);
        } else {
            int p = atomicAdd(&s_n, 1);                  // smem atomic, cheap
            if (p < SBUF) s_buf[p] = make_int2(s, d);
            else          Lg[atomicAdd(cg, 1)] = make_int2(s, d);  // overflow fallback
            if (MODE == 1) add_f1(s); else add_f0(s);
        }
    };

    const int gt = blockIdx.x * 1024 + tid;
    if (i64) {
        const long long* dst = (const long long*)ei + E;
        bool va = ((((size_t)dst) & 15) == 0);
        int V = E >> 1;
        if (va) {
            const longlong2* dst2 = (const longlong2*)dst;
            int base = gt * 8;
            if (base + 8 <= V) {
                longlong2 dd[8];
                #pragma unroll
                for (int j = 0; j < 8; j++) dd[j] = dst2[base + j];     // MLP=8
                #pragma unroll
                for (int j = 0; j < 8; j++) {
                    process(2 * (base + j),     (int)dd[j].x);
                    process(2 * (base + j) + 1, (int)dd[j].y);
                }
            } else {
                for (int j = 0; j < 8; j++) {
                    int v = base + j;
                    if (v < V) { longlong2 dd = dst2[v];
                        process(2 * v, (int)dd.x); process(2 * v + 1, (int)dd.y); }
                }
            }
            int e = 2 * V + gt;
            if (e < E) process(e, (int)dst[e]);
        } else {
            for (int e = gt; e < E; e += gridDim.x * 1024) process(e, (int)dst[e]);
        }
    } else {
        const int* dst = (const int*)ei + E;
        bool va = ((((size_t)dst) & 15) == 0);
        int V = E >> 2;
        if (va) {
            const int4* dst4 = (const int4*)dst;
            int base = gt * 8;          // up to 32 edges/thread for int32
            #pragma unroll
            for (int j = 0; j < 8; j++) {
                int v = base + j;
                if (v < V) {
                    int4 dd = dst4[v];
                    process(4 * v,     dd.x); process(4 * v + 1, dd.y);
                    process(4 * v + 2, dd.z); process(4 * v + 3, dd.w);
                }
            }
            for (int e = 4 * V + gt; e < E; e += gridDim.x * 1024) process(e, dst[e]);
        } else {
            for (int e = gt; e < E; e += gridDim.x * 1024) process(e, dst[e]);
        }
    }

    // flush per-block edge buffer with ONE global counter reservation
    if (MODE == 1 || MODE == 2) {
        __syncthreads();
        int n = (s_n < SBUF) ? s_n : SBUF;
        if (tid == 0) s_base = atomicAdd(cg, n);
        __syncthreads();
        for (int i = tid; i < n; i += 1024) Lg[s_base + i] = s_buf[i];
    }
}

// ---------------- y0 = x @ W1 + dinv for F0 nodes (warp per node) ---------------
__global__ void __launch_bounds__(256) k_y0(const float* __restrict__ x,
                                            const float* __restrict__ W1) {
    int wid  = (blockIdx.x * 256 + threadIdx.x) >> 5;
    int lane = threadIdx.x & 31;
    int nw   = (gridDim.x * 256) >> 5;
    int cnt  = g_c0;
    for (int i = wid; i < cnt; i += nw) {
        int n = g_list0[i];                              // broadcast load
        if (lane == 0) g_dinv[n] = rsqrtf(g_deg[n] + 1.0f);  // +1 self-loop
        const float* xr = x + (size_t)n * INDIM;
        float xv0 = xr[lane], xv1 = xr[lane + 32], xv2 = xr[lane + 64], xv3 = xr[lane + 96];
        float acc = 0.f;
        #pragma unroll
        for (int k = 0; k < 32; k++)
            acc = fmaf(__shfl_sync(0xffffffffu, xv0, k), W1[(k      ) * HID + lane], acc);
        #pragma unroll
        for (int k = 0; k < 32; k++)
            acc = fmaf(__shfl_sync(0xffffffffu, xv1, k), W1[(k +  32) * HID + lane], acc);
        #pragma unroll
        for (int k = 0; k < 32; k++)
            acc = fmaf(__shfl_sync(0xffffffffu, xv2, k), W1[(k +  64) * HID + lane], acc);
        #pragma unroll
        for (int k = 0; k < 32; k++)
            acc = fmaf(__shfl_sync(0xffffffffu, xv3, k), W1[(k +  96) * HID + lane], acc);
        g_y0[(size_t)n * HID + lane] = acc;
    }
}

// ---------------- edge aggregation: A[dst] += dinv[s]*dinv[d]*Y[src] ------------
__device__ __forceinline__ void agg_edges(const int2* __restrict__ L, int cnt,
                                          const float* __restrict__ Y, float* __restrict__ A,
                                          int warp, int nwarps, int lane) {
    for (int i = warp; i < cnt; i += nwarps) {
        int2 ed; float w = 0.f;
        if (lane == 0) { ed = L[i]; w = g_dinv[ed.x] * g_dinv[ed.y]; }
        ed.x = __shfl_sync(0xffffffffu, ed.x, 0);
        ed.y = __shfl_sync(0xffffffffu, ed.y, 0);
        w    = __shfl_sync(0xffffffffu, w, 0);
        atomicAdd(&A[(size_t)ed.y * HID + lane], w * Y[(size_t)ed.x * HID + lane]);
    }
}

__global__ void __launch_bounds__(256) k_agg1() {
    int warp = (blockIdx.x * 256 + threadIdx.x) >> 5;
    int lane = threadIdx.x & 31;
    int nw   = (gridDim.x * 256) >> 5;
    agg_edges(g_L1, g_cL1, g_y0, g_a1, warp, nw, lane);
}

// ------- node update: h = relu(A + dinv^2*Yin + b); Yout = h @ W (32x32) --------
__device__ __forceinline__ void layer_nodes(const int* __restrict__ list, int cnt,
                                            const float* __restrict__ A,
                                            const float* __restrict__ Yin,
                                            const float* __restrict__ b,
                                            const float* __restrict__ W,
                                            float* __restrict__ Yout,
                                            int warp, int nwarps, int lane) {
    for (int i = warp; i < cnt; i += nwarps) {
        int n = list[i];
        float dv = g_dinv[n];
        float h = A[(size_t)n * HID + lane] + dv * dv * Yin[(size_t)n * HID + lane] + b[lane];
        h = fmaxf(h, 0.f);
        float acc = 0.f;
        #pragma unroll
        for (int k = 0; k < HID; k++)
            acc = fmaf(__shfl_sync(0xffffffffu, h, k), W[k * HID + lane], acc);
        Yout[(size_t)n * HID + lane] = acc;
    }
}

// ---------------- tail: layers 1-3 tiny work + final + state reset --------------
__global__ void __launch_bounds__(1024) k_tail(const float* __restrict__ b1,
                                               const float* __restrict__ W2,
                                               const float* __restrict__ b2,
                                               const float* __restrict__ W3,
                                               const float* __restrict__ b3,
                                               const float* __restrict__ Wfc,
                                               const float* __restrict__ bfc,
                                               float* __restrict__ out) {
    __shared__ float s_z[2 * HID];
    const int tid  = threadIdx.x;
    const int warp = tid >> 5;            // 0..31
    const int lane = tid & 31;

    // layer-1 node update -> y1 (|F1| ~ hundreds)
    layer_nodes(g_list1, g_c1, g_a1, g_y0, b1, W2, g_y1, warp, 32, lane);
    __threadfence(); __syncthreads();

    // agg2 over L2 (~hundreds of edges)
    agg_edges(g_L2, g_cL2, g_y1, g_a2, warp, 32, lane);
    __threadfence(); __syncthreads();

    // layer-2 node update -> y2 (|F2| ~ tens)
    layer_nodes(g_list2, g_c2, g_a2, g_y1, b2, W3, g_y2, warp, 32, lane);
    __threadfence(); __syncthreads();

    // agg3 over L3 (edges into nodes 0,1)
    agg_edges(g_L3, g_cL3, g_y2, g_a3, warp, 32, lane);
    __threadfence(); __syncthreads();

    // final: h3 at {0,1}; z = concat; out = z @ Wfc + bfc
    if (tid < 2 * HID) {
        int node = tid >> 5;
        float dv = g_dinv[node];
        float h = g_a3[tid] + dv * dv * g_y2[(size_t)node * HID + lane] + b3[lane];
        s_z[tid] = fmaxf(h, 0.f);
    }
    __syncthreads();
    if (tid < 64) {
        float acc = bfc[tid];
        #pragma unroll
        for (int i = 0; i < 2 * HID; i++)
            acc = fmaf(s_z[i], Wfc[i * 64 + tid], acc);
        out[tid] = acc;
    }
    __syncthreads();

    // ---- reset all touched state for the next graph replay ----
    int c0 = g_c0;
    __syncthreads();
    for (int i = tid; i < c0; i += 1024) g_deg[g_list0[i]] = 0.f;
    for (int w = tid; w < BMW; w += 1024) { g_bm0[w] = 0u; g_bm1[w] = 0u; g_bm2[w] = 0u; }
    if (tid < 2 * HID) g_a3[tid] = 0.f;
    __syncthreads();
    if (tid == 0) { g_c0 = 0; g_c1 = 0; g_c2 = 0; g_cL1 = 0; g_cL2 = 0; g_cL3 = 0; }
}

// ---------------- launcher: 7 kernels ------------------------------------------
extern "C" void kernel_launch(void* const* d_in, const int* in_sizes, int n_in,
                              void* d_out, int out_size) {
    const float* x   = (const float*)d_in[0];
    const void*  ei  = d_in[1];               // int64 or int32, auto-detected
    const float* W1  = (const float*)d_in[2];
    const float* b1  = (const float*)d_in[3];
    const float* W2  = (const float*)d_in[4];
    const float* b2  = (const float*)d_in[5];
    const float* W3  = (const float*)d_in[6];
    const float* b3  = (const float*)d_in[7];
    const float* Wfc = (const float*)d_in[8];
    const float* bfc = (const float*)d_in[9];
    float* out = (float*)d_out;

    int E  = in_sizes[1] / 2;
    int sb = (E + 16383) / 16384;             // 1024 thr x 16 edges/thread

    k_scan<0><<<sb, 1024>>>(ei, E);           // L3 edges + F2 frontier
    k_scan<1><<<sb, 1024>>>(ei, E);           // L2 edges + F1 frontier
    k_scan<2><<<sb, 1024>>>(ei, E);           // L1 edges + F0 frontier
    k_scan<3><<<sb, 1024>>>(ei, E);           // degrees (F0-filtered)
    k_y0   <<<256, 256>>>(x, W1);             // dinv + x@W1 on F0
    k_agg1 <<<256, 256>>>();                  // layer-1 message aggregation
    k_tail <<<1, 1024>>>(b1, W2, b2, W3, b3, Wfc, bfc, out);
}

// round 11
// speedup vs baseline: 1.0920x; 1.0920x over previous
#include <cuda_runtime.h>

#define HID   32
#define INDIM 128
#define NMAX  100000
#define EMAX  1600000
#define BMW   ((NMAX + 31) / 32)    // 3125 bitmap words = 12.5 KB
#define SBUF  2048                  // per-block smem edge buffer

// ---------------- static device scratch (no allocations allowed) ----------------
// Everything mutable is reset by k_tail each call, so every graph replay sees
// identical initial state. Statics start zeroed.
__device__ __align__(16) float        g_deg [NMAX];   // only F0 entries touched; reset via list0
__device__ __align__(16) float        g_dinv[NMAX];   // recomputed for F0 each call
__device__ __align__(16) unsigned int g_bm0[BMW], g_bm1[BMW], g_bm2[BMW];  // reset in tail
__device__ int  g_list0[NMAX], g_list1[NMAX], g_list2[NMAX];
__device__ int2 g_L1[EMAX], g_L2[EMAX], g_L3[EMAX];
__device__ int  g_c0, g_c1, g_c2, g_cL1, g_cL2, g_cL3;                    // reset in tail
__device__ __align__(16) float g_y0[(size_t)NMAX * HID];
__device__ __align__(16) float g_y1[(size_t)NMAX * HID];
__device__ __align__(16) float g_y2[(size_t)NMAX * HID];
__device__ __align__(16) float g_a1[(size_t)NMAX * HID];  // rows zeroed on frontier insert
__device__ __align__(16) float g_a2[(size_t)NMAX * HID];
__device__ __align__(16) float g_a3[2 * HID];             // reset in tail

// ---------------- frontier insertion: atomicOr dedupe + cascade ----------------
__device__ __forceinline__ void add_f0(int n) {
    unsigned int b = 1u << (n & 31);
    if (!(atomicOr(&g_bm0[n >> 5], b) & b))
        g_list0[atomicAdd(&g_c0, 1)] = n;
}
__device__ __forceinline__ void add_f1(int n) {
    unsigned int b = 1u << (n & 31);
    if (!(atomicOr(&g_bm1[n >> 5], b) & b)) {
        g_list1[atomicAdd(&g_c1, 1)] = n;
        float4* a = (float4*)(g_a1 + (size_t)n * HID);
        float4 z = make_float4(0.f, 0.f, 0.f, 0.f);
        #pragma unroll
        for (int j = 0; j < 8; j++) a[j] = z;
        add_f0(n);
    }
}
__device__ __forceinline__ void add_f2(int n) {
    unsigned int b = 1u << (n & 31);
    if (!(atomicOr(&g_bm2[n >> 5], b) & b)) {
        g_list2[atomicAdd(&g_c2, 1)] = n;
        float4* a = (float4*)(g_a2 + (size_t)n * HID);
        float4 z = make_float4(0.f, 0.f, 0.f, 0.f);
        #pragma unroll
        for (int j = 0; j < 8; j++) a[j] = z;
        add_f1(n);
    }
}

// ---------------- edge scan kernel, templated on phase --------------------------
// MODE 0: dst<2    -> L3 + cascade F2   (unmasked)
// MODE 1: bm2[dst] -> L2 + cascade F1   (smem bitmap)
// MODE 2: bm1[dst] -> L1 + cascade F0
// MODE 3: bm0[dst] -> deg atomic only
// WARP-COALESCED vector loads: warp processes vectors v0 + j*32 + lane, so every
// LDG.128 covers 32 consecutive 16B elements (4 lines), MLP=8 per thread.
template<int MODE>
__global__ void __launch_bounds__(1024) k_scan(const void* __restrict__ ei, int E) {
    __shared__ unsigned int s_bm[BMW];
    __shared__ int2 s_buf[(MODE == 1 || MODE == 2) ? SBUF : 1];
    __shared__ int  s_n, s_base, s_i64;

    const int tid  = threadIdx.x;
    const int lane = tid & 31;
    if (tid == 0) { s_n = 0; s_i64 = 1; }
    __syncthreads();

    // parallel int64/int32 detection: int64 => high word of every element is 0
    {
        const unsigned int* w = (const unsigned int*)ei;
        int lim = (2 * E < 2048) ? 2 * E : 2048;
        for (int k = 2 * tid + 1; k < lim; k += 2048)
            if (w[k]) s_i64 = 0;                   // benign same-value race
    }
    if (MODE >= 1) {
        const unsigned int* bm = (MODE == 1) ? g_bm2 : (MODE == 2) ? g_bm1 : g_bm0;
        for (int i = tid; i < BMW; i += 1024) s_bm[i] = bm[i];
    }
    __syncthreads();
    const int i64 = s_i64;

    int2* Lg = (MODE == 0) ? g_L3 : (MODE == 1) ? g_L2 : g_L1;
    int*  cg = (MODE == 0) ? &g_cL3 : (MODE == 1) ? &g_cL2 : &g_cL1;

    if (MODE == 0 && blockIdx.x == 0 && tid == 0) { add_f2(0); add_f2(1); }

    auto process = [&](int e, int d) {
        bool hit = (MODE == 0) ? (d < 2) : (((s_bm[d >> 5] >> (d & 31)) & 1u) != 0);
        if (!hit) return;
        if (MODE == 3) { atomicAdd(&g_deg[d], 1.0f); return; }
        int s = i64 ? (int)((const long long*)ei)[e] : ((const int*)ei)[e];
        if (MODE == 0) {
            Lg[atomicAdd(cg, 1)] = make_int2(s, d);      // ~tens of hits total
            add_f2(s);
        } else {
            int p = atomicAdd(&s_n, 1);                  // smem atomic, cheap
            if (p < SBUF) s_buf[p] = make_int2(s, d);
            else          Lg[atomicAdd(cg, 1)] = make_int2(s, d);  // overflow fallback
            if (MODE == 1) add_f1(s); else add_f0(s);
        }
    };

    const int gwarp  = (blockIdx.x * 1024 + tid) >> 5;
    const int nwarps = (gridDim.x * 1024) >> 5;
    const int gt     = blockIdx.x * 1024 + tid;
    const int gs     = gridDim.x * 1024;

    if (i64) {
        const long long* dst = (const long long*)ei + E;
        if ((((size_t)dst) & 15) == 0) {
            const longlong2* dst2 = (const longlong2*)dst;
            const int V = E >> 1;
            // warp-coalesced: batch of 8 vector loads, lanes interleaved
            for (int v0 = gwarp * 256; v0 < V; v0 += nwarps * 256) {
                longlong2 dd[8];
                int vv[8];
                #pragma unroll
                for (int j = 0; j < 8; j++) {
                    vv[j] = v0 + j * 32 + lane;
                    if (vv[j] < V) dd[j] = dst2[vv[j]];          // MLP=8, 4 lines/LDG
                }
                #pragma unroll
                for (int j = 0; j < 8; j++) {
                    if (vv[j] < V) {
                        process(2 * vv[j],     (int)dd[j].x);
                        process(2 * vv[j] + 1, (int)dd[j].y);
                    }
                }
            }
            for (int e = 2 * V + gt; e < E; e += gs) process(e, (int)dst[e]);
        } else {
            for (int e = gt; e < E; e += gs) process(e, (int)dst[e]);
        }
    } else {
        const int* dst = (const int*)ei + E;
        if ((((size_t)dst) & 15) == 0) {
            const int4* dst4 = (const int4*)dst;
            const int V = E >> 2;
            for (int v0 = gwarp * 256; v0 < V; v0 += nwarps * 256) {
                int4 dd[8];
                int vv[8];
                #pragma unroll
                for (int j = 0; j < 8; j++) {
                    vv[j] = v0 + j * 32 + lane;
                    if (vv[j] < V) dd[j] = dst4[vv[j]];
                }
                #pragma unroll
                for (int j = 0; j < 8; j++) {
                    if (vv[j] < V) {
                        process(4 * vv[j],     dd[j].x);
                        process(4 * vv[j] + 1, dd[j].y);
                        process(4 * vv[j] + 2, dd[j].z);
                        process(4 * vv[j] + 3, dd[j].w);
                    }
                }
            }
            for (int e = 4 * V + gt; e < E; e += gs) process(e, dst[e]);
        } else {
            for (int e = gt; e < E; e += gs) process(e, dst[e]);
        }
    }

    // flush per-block edge buffer with ONE global counter reservation
    if (MODE == 1 || MODE == 2) {
        __syncthreads();
        int n = (s_n < SBUF) ? s_n : SBUF;
        if (tid == 0) s_base = atomicAdd(cg, n);
        __syncthreads();
        for (int i = tid; i < n; i += 1024) Lg[s_base + i] = s_buf[i];
    }
}

// ---------------- y0 = x @ W1 + dinv for F0 nodes (warp per node) ---------------
__global__ void __launch_bounds__(256) k_y0(const float* __restrict__ x,
                                            const float* __restrict__ W1) {
    int wid  = (blockIdx.x * 256 + threadIdx.x) >> 5;
    int lane = threadIdx.x & 31;
    int nw   = (gridDim.x * 256) >> 5;
    int cnt  = g_c0;
    for (int i = wid; i < cnt; i += nw) {
        int n = g_list0[i];                                  // broadcast load
        if (lane == 0) g_dinv[n] = rsqrtf(g_deg[n] + 1.0f);  // +1 self-loop
        const float* xr = x + (size_t)n * INDIM;
        float xv0 = xr[lane], xv1 = xr[lane + 32], xv2 = xr[lane + 64], xv3 = xr[lane + 96];
        float acc = 0.f;
        #pragma unroll
        for (int k = 0; k < 32; k++)
            acc = fmaf(__shfl_sync(0xffffffffu, xv0, k), W1[(k      ) * HID + lane], acc);
        #pragma unroll
        for (int k = 0; k < 32; k++)
            acc = fmaf(__shfl_sync(0xffffffffu, xv1, k), W1[(k +  32) * HID + lane], acc);
        #pragma unroll
        for (int k = 0; k < 32; k++)
            acc = fmaf(__shfl_sync(0xffffffffu, xv2, k), W1[(k +  64) * HID + lane], acc);
        #pragma unroll
        for (int k = 0; k < 32; k++)
            acc = fmaf(__shfl_sync(0xffffffffu, xv3, k), W1[(k +  96) * HID + lane], acc);
        g_y0[(size_t)n * HID + lane] = acc;
    }
}

// ---------------- edge aggregation: A[dst] += dinv[s]*dinv[d]*Y[src] ------------
__device__ __forceinline__ void agg_edges(const int2* __restrict__ L, int cnt,
                                          const float* __restrict__ Y, float* __restrict__ A,
                                          int warp, int nwarps, int lane) {
    for (int i = warp; i < cnt; i += nwarps) {
        int2 ed; float w = 0.f;
        if (lane == 0) { ed = L[i]; w = g_dinv[ed.x] * g_dinv[ed.y]; }
        ed.x = __shfl_sync(0xffffffffu, ed.x, 0);
        ed.y = __shfl_sync(0xffffffffu, ed.y, 0);
        w    = __shfl_sync(0xffffffffu, w, 0);
        atomicAdd(&A[(size_t)ed.y * HID + lane], w * Y[(size_t)ed.x * HID + lane]);
    }
}

__global__ void __launch_bounds__(256) k_agg1() {
    int warp = (blockIdx.x * 256 + threadIdx.x) >> 5;
    int lane = threadIdx.x & 31;
    int nw   = (gridDim.x * 256) >> 5;
    agg_edges(g_L1, g_cL1, g_y0, g_a1, warp, nw, lane);
}

// ------- node update: h = relu(A + dinv^2*Yin + b); Yout = h @ W (32x32) --------
__device__ __forceinline__ void layer_nodes(const int* __restrict__ list, int cnt,
                                            const float* __restrict__ A,
                                            const float* __restrict__ Yin,
                                            const float* __restrict__ b,
                                            const float* __restrict__ W,
                                            float* __restrict__ Yout,
                                            int warp, int nwarps, int lane) {
    for (int i = warp; i < cnt; i += nwarps) {
        int n = list[i];
        float dv = g_dinv[n];
        float h = A[(size_t)n * HID + lane] + dv * dv * Yin[(size_t)n * HID + lane] + b[lane];
        h = fmaxf(h, 0.f);
        float acc = 0.f;
        #pragma unroll
        for (int k = 0; k < HID; k++)
            acc = fmaf(__shfl_sync(0xffffffffu, h, k), W[k * HID + lane], acc);
        Yout[(size_t)n * HID + lane] = acc;
    }
}

// ---------------- tail: layers 1-3 tiny work + final + state reset --------------
__global__ void __launch_bounds__(1024) k_tail(const float* __restrict__ b1,
                                               const float* __restrict__ W2,
                                               const float* __restrict__ b2,
                                               const float* __restrict__ W3,
                                               const float* __restrict__ b3,
                                               const float* __restrict__ Wfc,
                                               const float* __restrict__ bfc,
                                               float* __restrict__ out) {
    __shared__ float s_z[2 * HID];
    const int tid  = threadIdx.x;
    const int warp = tid >> 5;            // 0..31
    const int lane = tid & 31;

    // layer-1 node update -> y1 (|F1| ~ hundreds)
    layer_nodes(g_list1, g_c1, g_a1, g_y0, b1, W2, g_y1, warp, 32, lane);
    __threadfence(); __syncthreads();

    // agg2 over L2 (~hundreds of edges)
    agg_edges(g_L2, g_cL2, g_y1, g_a2, warp, 32, lane);
    __threadfence(); __syncthreads();

    // layer-2 node update -> y2 (|F2| ~ tens)
    layer_nodes(g_list2, g_c2, g_a2, g_y1, b2, W3, g_y2, warp, 32, lane);
    __threadfence(); __syncthreads();

    // agg3 over L3 (edges into nodes 0,1)
    agg_edges(g_L3, g_cL3, g_y2, g_a3, warp, 32, lane);
    __threadfence(); __syncthreads();

    // final: h3 at {0,1}; z = concat; out = z @ Wfc + bfc
    if (tid < 2 * HID) {
        int node = tid >> 5;
        float dv = g_dinv[node];
        float h = g_a3[tid] + dv * dv * g_y2[(size_t)node * HID + lane] + b3[lane];
        s_z[tid] = fmaxf(h, 0.f);
    }
    __syncthreads();
    if (tid < 64) {
        float acc = bfc[tid];
        #pragma unroll
        for (int i = 0; i < 2 * HID; i++)
            acc = fmaf(s_z[i], Wfc[i * 64 + tid], acc);
        out[tid] = acc;
    }
    __syncthreads();

    // ---- reset all touched state for the next graph replay ----
    int c0 = g_c0;
    __syncthreads();
    for (int i = tid; i < c0; i += 1024) g_deg[g_list0[i]] = 0.f;
    for (int w = tid; w < BMW; w += 1024) { g_bm0[w] = 0u; g_bm1[w] = 0u; g_bm2[w] = 0u; }
    if (tid < 2 * HID) g_a3[tid] = 0.f;
    __syncthreads();
    if (tid == 0) { g_c0 = 0; g_c1 = 0; g_c2 = 0; g_cL1 = 0; g_cL2 = 0; g_cL3 = 0; }
}

// ---------------- launcher: 7 kernels ------------------------------------------
extern "C" void kernel_launch(void* const* d_in, const int* in_sizes, int n_in,
                              void* d_out, int out_size) {
    const float* x   = (const float*)d_in[0];
    const void*  ei  = d_in[1];               // int64 or int32, auto-detected
    const float* W1  = (const float*)d_in[2];
    const float* b1  = (const float*)d_in[3];
    const float* W2  = (const float*)d_in[4];
    const float* b2  = (const float*)d_in[5];
    const float* W3  = (const float*)d_in[6];
    const float* b3  = (const float*)d_in[7];
    const float* Wfc = (const float*)d_in[8];
    const float* bfc = (const float*)d_in[9];
    float* out = (float*)d_out;

    int E  = in_sizes[1] / 2;
    // grid sized for the int64 path (V = E/2 vectors, 8192 vectors per block);
    // int32 path simply finishes in half the iterations (grid-stride loops).
    int sb = ((E >> 1) + 8191) / 8192;
    if (sb < 1) sb = 1;

    k_scan<0><<<sb, 1024>>>(ei, E);           // L3 edges + F2 frontier
    k_scan<1><<<sb, 1024>>>(ei, E);           // L2 edges + F1 frontier
    k_scan<2><<<sb, 1024>>>(ei, E);           // L1 edges + F0 frontier
    k_scan<3><<<sb, 1024>>>(ei, E);           // degrees (F0-filtered)
    k_y0   <<<256, 256>>>(x, W1);             // dinv + x@W1 on F0
    k_agg1 <<<256, 256>>>();                  // layer-1 message aggregation
    k_tail <<<1, 1024>>>(b1, W2, b2, W3, b3, Wfc, bfc, out);
}

// round 14
// speedup vs baseline: 1.2173x; 1.1148x over previous
#include <cuda_runtime.h>

#define HID   32
#define INDIM 128
#define NMAX  100000
#define EMAX  1600000

// ---------------- static device scratch (no allocations allowed) ----------------
// All mutable state is reset within the launch sequence (masks/deg in k_agg1,
// counters/a3 in k_tailC), so every graph replay sees identical initial state.
__device__ __align__(16) float         g_deg [NMAX];   // reset in k_agg1
__device__ __align__(16) float         g_dinv[NMAX];   // recomputed for F0 nodes
__device__ __align__(16) unsigned char g_m0[NMAX], g_m1[NMAX], g_m2[NMAX]; // reset in k_agg1
__device__ int  g_list1[NMAX], g_list2[NMAX];
__device__ int2 g_L1[EMAX], g_L2[EMAX], g_L3[EMAX];
__device__ int  g_c1, g_c2, g_cL1, g_cL2, g_cL3;       // reset in k_tailC
__device__ __align__(16) float g_y0[(size_t)NMAX * HID];
__device__ __align__(16) float g_y1[(size_t)NMAX * HID];
__device__ __align__(16) float g_y2[(size_t)NMAX * HID];
__device__ __align__(16) float g_a1[(size_t)NMAX * HID];   // rows zeroed in k_nodeB
__device__ __align__(16) float g_a2[(size_t)NMAX * HID];   // rows zeroed in k_nodeA
__device__ __align__(16) float g_a3[2 * HID];              // reset in k_tailC

// ---- per-block parallel int64/int32 detection (int64 => all high words zero) ---
__device__ __forceinline__ int detect_i64(const void* ei, int E, int* s_flag) {
    if (threadIdx.x == 0) *s_flag = 1;
    __syncthreads();
    const unsigned int* w = (const unsigned int*)ei;
    int lim = (2 * E < 2048) ? 2 * E : 2048;
    for (int k = 2 * threadIdx.x + 1; k < lim; k += 2 * blockDim.x)
        if (w[k]) *s_flag = 0;                     // benign same-value race
    __syncthreads();
    return *s_flag;
}
__device__ __forceinline__ int ld_idx(const void* ei, int i64, size_t pos) {
    return i64 ? (int)((const long long*)ei)[pos] : ((const int*)ei)[pos];
}

// ---------------- scan A: edges with dst<2 -> L3; mark m2[src]; seed m2 ---------
__global__ void __launch_bounds__(256) k_scanA(const void* __restrict__ ei, int E) {
    __shared__ int s_f;
    int i64 = detect_i64(ei, E, &s_f);
    int e = blockIdx.x * 256 + threadIdx.x;
    if (e == 0) { g_m2[0] = 1; g_m2[1] = 1; }      // self-loops of output nodes
    if (e >= E) return;
    int d = ld_idx(ei, i64, (size_t)E + e);
    if (d < 2) {
        int s = ld_idx(ei, i64, (size_t)e);
        g_L3[atomicAdd(&g_cL3, 1)] = make_int2(s, d);
        g_m2[s] = 1;
    }
}

// ---------------- node A: compact m2 -> list2; m1 = m2; zero a2 rows ------------
__global__ void __launch_bounds__(256) k_nodeA(int N) {
    int n = blockIdx.x * 256 + threadIdx.x;
    if (n >= N) return;
    unsigned char m = g_m2[n];
    g_m1[n] = m;
    if (m) {
        g_list2[atomicAdd(&g_c2, 1)] = n;
        float4* a = (float4*)(g_a2 + (size_t)n * HID);
        float4 z = make_float4(0.f, 0.f, 0.f, 0.f);
        #pragma unroll
        for (int j = 0; j < 8; j++) a[j] = z;
    }
}

// ---------------- scan B: edges into F2 -> L2; mark m1[src] ---------------------
__global__ void __launch_bounds__(256) k_scanB(const void* __restrict__ ei, int E) {
    __shared__ int s_f;
    int i64 = detect_i64(ei, E, &s_f);
    int e = blockIdx.x * 256 + threadIdx.x;
    if (e >= E) return;
    int d = ld_idx(ei, i64, (size_t)E + e);
    if (g_m2[d]) {
        int s = ld_idx(ei, i64, (size_t)e);
        g_L2[atomicAdd(&g_cL2, 1)] = make_int2(s, d);
        g_m1[s] = 1;
    }
}

// ---------------- node B: compact m1 -> list1; m0 = m1; zero a1 rows ------------
__global__ void __launch_bounds__(256) k_nodeB(int N) {
    int n = blockIdx.x * 256 + threadIdx.x;
    if (n >= N) return;
    unsigned char m = g_m1[n];
    g_m0[n] = m;
    if (m) {
        g_list1[atomicAdd(&g_c1, 1)] = n;
        float4* a = (float4*)(g_a1 + (size_t)n * HID);
        float4 z = make_float4(0.f, 0.f, 0.f, 0.f);
        #pragma unroll
        for (int j = 0; j < 8; j++) a[j] = z;
    }
}

// ------- scan C: deg[dst]++ for EVERY edge; edges into F1 -> L1; mark m0 --------
__global__ void __launch_bounds__(256) k_scanC(const void* __restrict__ ei, int E) {
    __shared__ int s_f;
    int i64 = detect_i64(ei, E, &s_f);
    int e = blockIdx.x * 256 + threadIdx.x;
    if (e >= E) return;
    int d = ld_idx(ei, i64, (size_t)E + e);
    atomicAdd(&g_deg[d], 1.0f);                    // spread REDG, overlaps mask gather
    if (g_m1[d]) {
        int s = ld_idx(ei, i64, (size_t)e);
        g_L1[atomicAdd(&g_cL1, 1)] = make_int2(s, d);
        g_m0[s] = 1;
    }
}

// ------ y0 = x @ W1 + dinv for m0-marked nodes (ballot over 32-node chunks) -----
__global__ void __launch_bounds__(256) k_y0(const float* __restrict__ x,
                                            const float* __restrict__ W1, int N) {
    int gwarp  = (blockIdx.x * 256 + threadIdx.x) >> 5;
    int lane   = threadIdx.x & 31;
    int nwarps = (gridDim.x * 256) >> 5;
    int nchunk = (N + 31) / 32;
    for (int c = gwarp; c < nchunk; c += nwarps) {
        int n0 = c * 32;
        int nn = n0 + lane;
        unsigned char m = (nn < N) ? g_m0[nn] : 0;      // one coalesced 32B load
        unsigned int bits = __ballot_sync(0xffffffffu, m != 0);
        while (bits) {
            int b = __ffs(bits) - 1;
            bits &= bits - 1;
            int n = n0 + b;
            if (lane == 0) g_dinv[n] = rsqrtf(g_deg[n] + 1.0f);  // +1 self-loop
            const float* xr = x + (size_t)n * INDIM;
            float xv0 = xr[lane], xv1 = xr[lane + 32], xv2 = xr[lane + 64], xv3 = xr[lane + 96];
            float acc = 0.f;
            #pragma unroll
            for (int k = 0; k < 32; k++)
                acc = fmaf(__shfl_sync(0xffffffffu, xv0, k), W1[(k      ) * HID + lane], acc);
            #pragma unroll
            for (int k = 0; k < 32; k++)
                acc = fmaf(__shfl_sync(0xffffffffu, xv1, k), W1[(k +  32) * HID + lane], acc);
            #pragma unroll
            for (int k = 0; k < 32; k++)
                acc = fmaf(__shfl_sync(0xffffffffu, xv2, k), W1[(k +  64) * HID + lane], acc);
            #pragma unroll
            for (int k = 0; k < 32; k++)
                acc = fmaf(__shfl_sync(0xffffffffu, xv3, k), W1[(k +  96) * HID + lane], acc);
            g_y0[(size_t)n * HID + lane] = acc;
        }
    }
}

// ---------------- edge aggregation: A[dst] += dinv[s]*dinv[d]*Y[src] ------------
__device__ __forceinline__ void agg_edges(const int2* __restrict__ L, int cnt,
                                          const float* __restrict__ Y, float* __restrict__ A,
                                          int warp, int nwarps, int lane) {
    for (int i = warp; i < cnt; i += nwarps) {
        int2 ed = L[i];                              // all lanes same addr: broadcast
        float w = g_dinv[ed.x] * g_dinv[ed.y];
        atomicAdd(&A[(size_t)ed.y * HID + lane], w * Y[(size_t)ed.x * HID + lane]);
    }
}

// ------- agg1 over L1 + grid-wide reset of deg + masks (dead after k_y0) --------
__global__ void __launch_bounds__(256) k_agg1(int N) {
    int gt = blockIdx.x * 256 + threadIdx.x;
    int gs = gridDim.x * 256;
    for (int i = gt; i < N; i += gs) g_deg[i] = 0.f;
    int nw = (N + 3) / 4;
    unsigned int* m0 = (unsigned int*)g_m0;
    unsigned int* m1 = (unsigned int*)g_m1;
    unsigned int* m2 = (unsigned int*)g_m2;
    for (int i = gt; i < nw; i += gs) { m0[i] = 0u; m1[i] = 0u; m2[i] = 0u; }
    agg_edges(g_L1, g_cL1, g_y0, g_a1, gt >> 5, gs >> 5, threadIdx.x & 31);
}

// ------- node update: h = relu(A + dinv^2*Yin + b); Yout = h @ W (32x32) --------
__device__ __forceinline__ void layer_nodes(const int* __restrict__ list, int cnt,
                                            const float* __restrict__ A,
                                            const float* __restrict__ Yin,
                                            const float* __restrict__ b,
                                            const float* __restrict__ W,
                                            float* __restrict__ Yout,
                                            int warp, int nwarps, int lane) {
    for (int i = warp; i < cnt; i += nwarps) {
        int n = list[i];
        float dv = g_dinv[n];
        float h = A[(size_t)n * HID + lane] + dv * dv * Yin[(size_t)n * HID + lane] + b[lane];
        h = fmaxf(h, 0.f);
        float acc = 0.f;
        #pragma unroll
        for (int k = 0; k < HID; k++)
            acc = fmaf(__shfl_sync(0xffffffffu, h, k), W[k * HID + lane], acc);
        Yout[(size_t)n * HID + lane] = acc;
    }
}

// ---------------- layer-1 node update -> y1 (|F1| ~ hundreds) -------------------
__global__ void __launch_bounds__(256) k_layer1(const float* __restrict__ b1,
                                                const float* __restrict__ W2) {
    layer_nodes(g_list1, g_c1, g_a1, g_y0, b1, W2, g_y1,
                (blockIdx.x * 256 + threadIdx.x) >> 5, (gridDim.x * 256) >> 5,
                threadIdx.x & 31);
}

// ---------------- agg2 over L2 (~hundreds of edges) -----------------------------
__global__ void __launch_bounds__(256) k_agg2() {
    agg_edges(g_L2, g_cL2, g_y1, g_a2,
              (blockIdx.x * 256 + threadIdx.x) >> 5, (gridDim.x * 256) >> 5,
              threadIdx.x & 31);
}

// ------- tail: layer2 + agg3 + final GEMV + counter resets (single block) -------
__global__ void __launch_bounds__(256) k_tailC(const float* __restrict__ b2,
                                               const float* __restrict__ W3,
                                               const float* __restrict__ b3,
                                               const float* __restrict__ Wfc,
                                               const float* __restrict__ bfc,
                                               float* __restrict__ out) {
    __shared__ float s_z[2 * HID];
    const int tid  = threadIdx.x;
    const int warp = tid >> 5;                     // 0..7
    const int lane = tid & 31;

    // layer-2 node update -> y2 (|F2| ~ tens)
    layer_nodes(g_list2, g_c2, g_a2, g_y1, b2, W3, g_y2, warp, 8, lane);
    __threadfence(); __syncthreads();

    // agg3 over L3 (edges into nodes 0,1)
    agg_edges(g_L3, g_cL3, g_y2, g_a3, warp, 8, lane);
    __threadfence(); __syncthreads();

    // final: h3 at {0,1}; z = concat(h3[0], h3[1]); out = z @ Wfc + bfc
    if (tid < 2 * HID) {
        int node = tid >> 5;
        float dv = g_dinv[node];
        float h = g_a3[tid] + dv * dv * g_y2[(size_t)node * HID + lane] + b3[lane];
        s_z[tid] = fmaxf(h, 0.f);
    }
    __syncthreads();
    if (tid < 64) {
        float acc = bfc[tid];
        #pragma unroll
        for (int i = 0; i < 2 * HID; i++)
            acc = fmaf(s_z[i], Wfc[i * 64 + tid], acc);
        out[tid] = acc;
    }
    __syncthreads();

    // ---- reset remaining state for the next graph replay ----
    if (tid < 2 * HID) g_a3[tid] = 0.f;
    __syncthreads();
    if (tid == 0) { g_c1 = 0; g_c2 = 0; g_cL1 = 0; g_cL2 = 0; g_cL3 = 0; }
}

// ---------------- launcher: 10 kernels ------------------------------------------
extern "C" void kernel_launch(void* const* d_in, const int* in_sizes, int n_in,
                              void* d_out, int out_size) {
    const float* x   = (const float*)d_in[0];
    const void*  ei  = d_in[1];               // int64 or int32, auto-detected
    const float* W1  = (const float*)d_in[2];
    const float* b1  = (const float*)d_in[3];
    const float* W2  = (const float*)d_in[4];
    const float* b2  = (const float*)d_in[5];
    const float* W3  = (const float*)d_in[6];
    const float* b3  = (const float*)d_in[7];
    const float* Wfc = (const float*)d_in[8];
    const float* bfc = (const float*)d_in[9];
    float* out = (float*)d_out;

    int N  = in_sizes[0] / INDIM;
    int E  = in_sizes[1] / 2;
    int eb = (E + 255) / 256;
    int nb = (N + 255) / 256;

    k_scanA <<<eb, 256>>>(ei, E);             // L3 + F2 marks
    k_nodeA <<<nb, 256>>>(N);                 // list2, m1=m2, zero a2 rows
    k_scanB <<<eb, 256>>>(ei, E);             // L2 + F1 marks
    k_nodeB <<<nb, 256>>>(N);                 // list1, m0=m1, zero a1 rows
    k_scanC <<<eb, 256>>>(ei, E);             // degrees (all) + L1 + F0 marks
    k_y0    <<<512, 256>>>(x, W1, N);         // dinv + x@W1 on F0 (mask-driven)
    k_agg1  <<<256, 256>>>(N);                // layer-1 aggregation + mask/deg reset
    k_layer1<<<8, 256>>>(b1, W2);             // -> y1
    k_agg2  <<<4, 256>>>();                   // layer-2 aggregation
    k_tailC <<<1, 256>>>(b2, W3, b3, Wfc, bfc, out);
}